// round 6
// baseline (speedup 1.0000x reference)
#include <cuda_runtime.h>
#include <math.h>

// Problem constants
#define PB   32      // batch
#define PS   1024    // seq len
#define PD   3       // dsize
#define PNF  512     // n fourier samples
#define PNS  64      // noise size
#define PH   100     // hidden
#define PFS  256     // fourier feature size
#define PCH  16      // chunks along S
#define PLS  64      // S per chunk  (PS / PCH)
#define PNPT 2       // n per thread in k1 (256 per half-block / 128 threads)

#define MU_C   10.0f
#define LOG2C  (-3947.8417604357434f)   // -MU*T*(2*pi)^(D-1) = -100*(2pi)^2

// ---------------- scratch (no allocations allowed) ----------------
__device__ float4 g_womg4[PNF];                // (w0,w1,w2,0) per n
__device__ float  g_sumC[PB * PCH * PNF];      // per-chunk sums  (1 MB, L2-resident)
__device__ float  g_sumS[PB * PCH * PNF];
__device__ float  g_local0[PB * PS];           // within-chunk part, n in [0,256)
__device__ float  g_local1[PB * PS];           // within-chunk part, n in [256,512)

// ================= k_feat: fused MLP -> Womg  (one block per n) =============
__global__ __launch_bounds__(128) void k_feat(
    const float* __restrict__ noise, const float* __restrict__ W1,
    const float* __restrict__ b1,    const float* __restrict__ W2,
    const float* __restrict__ b2,    const float* __restrict__ W) {
    __shared__ float sh_noise[PNS];
    __shared__ float sh_hid[PH];
    __shared__ float sh_four[PFS];
    __shared__ float sh_red[4][3];

    int n = blockIdx.x;
    int tid = threadIdx.x;
    int lane = tid & 31, w = tid >> 5;

    if (tid < PNS) sh_noise[tid] = noise[n * PNS + tid];
    __syncthreads();

    if (tid < PH) {
        float acc = b1[tid];
        #pragma unroll 8
        for (int k = 0; k < PNS; k++) acc = fmaf(sh_noise[k], W1[k * PH + tid], acc);
        sh_hid[tid] = tanhf(acc);
    }
    __syncthreads();

    #pragma unroll
    for (int f = tid; f < PFS; f += 128) {
        float acc = b2[f];
        #pragma unroll 10
        for (int k = 0; k < PH; k++) acc = fmaf(sh_hid[k], W2[k * PFS + f], acc);
        sh_four[f] = tanhf(acc);
    }
    __syncthreads();

    float a0 = 0.f, a1 = 0.f, a2 = 0.f;
    #pragma unroll
    for (int f = tid; f < PFS; f += 128) {
        float fv = sh_four[f];
        a0 = fmaf(fv, W[f * PD + 0], a0);
        a1 = fmaf(fv, W[f * PD + 1], a1);
        a2 = fmaf(fv, W[f * PD + 2], a2);
    }
    #pragma unroll
    for (int d = 16; d >= 1; d >>= 1) {
        a0 += __shfl_xor_sync(0xffffffffu, a0, d);
        a1 += __shfl_xor_sync(0xffffffffu, a1, d);
        a2 += __shfl_xor_sync(0xffffffffu, a2, d);
    }
    if (lane == 0) { sh_red[w][0] = a0; sh_red[w][1] = a1; sh_red[w][2] = a2; }
    __syncthreads();
    if (tid == 0) {
        float r0 = sh_red[0][0] + sh_red[1][0] + sh_red[2][0] + sh_red[3][0];
        float r1 = sh_red[0][1] + sh_red[1][1] + sh_red[2][1] + sh_red[3][1];
        float r2 = sh_red[0][2] + sh_red[1][2] + sh_red[2][2] + sh_red[3][2];
        g_womg4[n] = make_float4(r0, r1, r2, 0.f);
    }
}

// ================= k1: within-chunk scan + chunk sums =======================
// grid = B*PCH*2 blocks (n-range split in half for occupancy), 128 threads,
// 2 fourier components per thread. Per-s partial -> padded shared (single STS,
// no in-loop SHFL chain), two-stage bulk column-reduce at the end.
__global__ __launch_bounds__(128) void k1(const float* __restrict__ X) {
    __shared__ float sx[PLS * PD];        // X chunk (192 floats)
    __shared__ float part[128][PLS + 1];  // [thread][s], padded (33 KB)
    __shared__ float half1[PLS];          // upper-half partial per s

    int blk = blockIdx.x;
    int h = blk & 1;                      // n half: 0 -> [0,256), 1 -> [256,512)
    int bc = blk >> 1;
    int b = bc / PCH, c = bc % PCH;
    int tid = threadIdx.x;

    const float* xp = X + (size_t)(b * PS + c * PLS) * PD;
    for (int i = tid; i < PLS * PD; i += 128) sx[i] = xp[i];

    float4 wv[PNPT];
    #pragma unroll
    for (int j = 0; j < PNPT; j++) wv[j] = g_womg4[h * 256 + j * 128 + tid];
    __syncthreads();

    float runC[PNPT] = {0.f, 0.f};
    float runS[PNPT] = {0.f, 0.f};

    #pragma unroll 4
    for (int ls = 0; ls < PLS; ls++) {
        float x0 = sx[ls * 3 + 0];
        float x1 = sx[ls * 3 + 1];
        float x2 = sx[ls * 3 + 2];
        float contrib = 0.f;
        #pragma unroll
        for (int j = 0; j < PNPT; j++) {
            float th = fmaf(x2, wv[j].z, fmaf(x1, wv[j].y, x0 * wv[j].x));
            float sn, cs;
            __sincosf(th, &sn, &cs);
            contrib = fmaf(cs, runC[j], contrib);
            contrib = fmaf(sn, runS[j], contrib);
            runC[j] += cs; runS[j] += sn;
        }
        part[tid][ls] = contrib;          // single STS, no dependency chain
    }

    int base = (b * PCH + c) * PNF + h * 256;
    #pragma unroll
    for (int j = 0; j < PNPT; j++) {
        g_sumC[base + j * 128 + tid] = runC[j];
        g_sumS[base + j * 128 + tid] = runS[j];
    }
    __syncthreads();

    // two-stage column reduce using all 128 threads:
    // stage 1: thread tid sums a 64-row half of column (tid & 63)
    {
        int col = tid & (PLS - 1);
        int r0 = (tid < PLS) ? 0 : 64;
        float t = 0.f;
        #pragma unroll 8
        for (int i = 0; i < 64; i++) t += part[r0 + i][col];
        if (tid < PLS) part[0][col] = t;   // reuse row 0 as scratch for lower half
        else           half1[col]   = t;
    }
    __syncthreads();
    if (tid < PLS) {
        float* dst = h ? g_local1 : g_local0;
        dst[b * PS + c * PLS + tid] = part[0][tid] + half1[tid];
    }
}

// ================= k3: cross-chunk term + finalize lam / loglik =============
// grid = B*PCH blocks, 256 threads, s handled by 4 threads (n split 4 ways).
// Phase trick: offC*cos(th) + offS*sin(th) = A*cos(th - phi), with A/phi
// computed once per (chunk,n) in the prologue -> 1 MUFU per inner iter, not 2.
__global__ __launch_bounds__(256) void k3(const float* __restrict__ X,
                                          const float* __restrict__ alpha,
                                          float* __restrict__ out) {
    __shared__ float4 swo[PNF];    // (w0,w1,w2,A)
    __shared__ float  sphi[PNF];   // phi
    __shared__ float  red[3][PLS]; // partials from n-splits 1..3

    int blk = blockIdx.x;
    int b = blk / PCH, c = blk % PCH;
    int tid = threadIdx.x;

    // per-n chunk-offset prefixes: sum predecessor chunk sums (L2 hits),
    // then fold into magnitude/phase form
    for (int n = tid; n < PNF; n += 256) {
        float oc = 0.f, os = 0.f;
        for (int cp = 0; cp < c; cp++) {
            int idx = (b * PCH + cp) * PNF + n;
            oc += g_sumC[idx];
            os += g_sumS[idx];
        }
        float4 v = g_womg4[n];
        v.w = sqrtf(fmaf(oc, oc, os * os));      // A
        swo[n] = v;
        sphi[n] = atan2f(os, oc);                // phi (0 when c == 0)
    }

    int sid = tid & (PLS - 1);       // s within chunk
    int p   = tid >> 6;              // n-split 0..3
    int s = c * PLS + sid;
    const float* xp = X + (size_t)(b * PS + s) * PD;
    float x0 = __ldg(xp + 0), x1 = __ldg(xp + 1), x2 = __ldg(xp + 2);
    __syncthreads();

    float acc = 0.f;
    int n0 = p * (PNF / 4);
    #pragma unroll 8
    for (int k = 0; k < PNF / 4; k++) {
        int n = n0 + k;
        float4 v = swo[n];                 // LDS.128 broadcast
        float ph = sphi[n];                // LDS.32 broadcast
        float th = fmaf(x2, v.z, fmaf(x1, v.y, x0 * v.x)) - ph;
        acc = fmaf(v.w, __cosf(th), acc);  // A * cos(th - phi)
    }
    if (p > 0) red[p - 1][sid] = acc;
    __syncthreads();

    if (p == 0) {
        float total = acc + red[0][sid] + red[1][sid] + red[2][sid]
                    + g_local0[b * PS + s] + g_local1[b * PS + s];
        float ksum = total * (1.0f / PNF);
        float lam = fmaf(alpha[0], ksum, MU_C);
        out[b * PS + s] = lam;                                   // lam [B,S]
        float ll = (x0 > 0.f) ? __logf(lam) : 0.f;
        out[PB * PS + b * (PS + 1) + s] = ll + LOG2C;            // loglik [B,S+1]
        if (c == 0 && sid == 0)
            out[PB * PS + b * (PS + 1) + PS] = LOG2C;            // loglik[b,S] tail
    }
}

// ---------------- launcher: bind inputs by unique element count ------------
extern "C" void kernel_launch(void* const* d_in, const int* in_sizes, int n_in,
                              void* d_out, int out_size) {
    // All 8 inputs have distinct sizes -> robust to ordering surprises.
    const float *X = 0, *noise = 0, *W1 = 0, *b1 = 0, *W2 = 0, *b2 = 0,
                *W = 0, *alpha = 0;
    for (int i = 0; i < n_in; i++) {
        const float* p = (const float*)d_in[i];
        switch (in_sizes[i]) {
            case PB * PS * PD:   X     = p; break;   // 98304
            case PNF * PNS:      noise = p; break;   // 32768
            case PNS * PH:       W1    = p; break;   // 6400
            case PH:             b1    = p; break;   // 100
            case PH * PFS:       W2    = p; break;   // 25600
            case PFS:            b2    = p; break;   // 256
            case PFS * PD:       W     = p; break;   // 768
            case 1:              alpha = p; break;   // 1
            default: break;
        }
    }
    float* out = (float*)d_out;

    k_feat<<<PNF, 128>>>(noise, W1, b1, W2, b2, W);
    k1    <<<PB * PCH * 2, 128>>>(X);
    k3    <<<PB * PCH, 256>>>(X, alpha, out);
}